// round 16
// baseline (speedup 1.0000x reference)
#include <cuda_runtime.h>
#include <cuda_bf16.h>
#include <cstdint>
#include <cstddef>
#include <climits>

// ---------------------------------------------------------------------------
// Problem shape (fixed by the dataset)
//   inputs:   [16, 2048, 1024] f32  -> M = 32768 tokens, D = 1024
//   codebook: [2048, 1024]     f32  -> K = 2048 codes
// Outputs concatenated (f32):
//   quantized  [32768,1024]  @ 0
//   qloss      [32768,2048]  @ 33554432   (scalar broadcast)
//   nn_idx     [32768]       @ 100663296  (as float)
//   codebook   [2048,1024]   @ 100696064
// ---------------------------------------------------------------------------
#define M_TOK   32768
#define K_CODE  2048
#define D_DIM   1024

#define QUANT_OFF 0
#define LOSS_OFF  33554432
#define NN_OFF    100663296
#define CB_OFF    100696064
#define LOSS_N    67108864
#define CB_N      2097152

#define NCAND 16

// ------------------------- scratch (device globals) ------------------------
__device__ __nv_bfloat16 g_logits[(size_t)M_TOK * K_CODE];   // 128 MiB (bf16)

#define RP_WARPS 4096          // 512 CTAs x 8 warps, 8 tokens per warp
__device__ float g_div_part[(size_t)RP_WARPS * K_CODE];   // 32 MiB per-warp partials
__device__ float g_h_part[RP_WARPS];
__device__ float g_acc_part[16];
__device__ int   g_nn[M_TOK];
__device__ float g_loss[1];
__device__ int   g_cand_cnt[M_TOK];
__device__ int   g_cand_idx[M_TOK][NCAND];

// int8 operands, per-row scaled, pre-tiled + pre-SW128-swizzled into 16KB
// blocks of [128 rows x 128 int8 cols] (= 128 rows x 128B; k-chunk = 128).
//   A blocks ordered [m_tile (256)][k_chunk (8)]
//   B blocks ordered [k_chunk (8)][n_block (16)]
__device__ uint4 g_Aq[(size_t)M_TOK * D_DIM / 16];   // 32 MiB
__device__ uint4 g_Bq[(size_t)K_CODE * D_DIM / 16];  // 2 MiB
__device__ float g_inva[M_TOK];    // per-token dequant scale (max/127)
__device__ float g_invb[K_CODE];   // per-code  dequant scale

// ------------------------- PTX helpers ---------------------------
__device__ __forceinline__ uint32_t smem_to_u32(const void* p) {
    uint32_t a;
    asm("{ .reg .u64 t; cvta.to.shared.u64 t, %1; cvt.u32.u64 %0, t; }" : "=r"(a) : "l"(p));
    return a;
}

__device__ __forceinline__ void cp_async16(uint32_t dst, const void* src) {
    asm volatile("cp.async.cg.shared.global [%0], [%1], 16;" :: "r"(dst), "l"(src) : "memory");
}
__device__ __forceinline__ void cp_commit() {
    asm volatile("cp.async.commit_group;" ::: "memory");
}
template <int N>
__device__ __forceinline__ void cp_wait() {
    asm volatile("cp.async.wait_group %0;" :: "n"(N) : "memory");
}

__device__ __forceinline__ void ldmatrix_x4(uint32_t& r0, uint32_t& r1,
                                            uint32_t& r2, uint32_t& r3, uint32_t addr) {
    asm volatile("ldmatrix.sync.aligned.m8n8.x4.shared.b16 {%0,%1,%2,%3}, [%4];"
                 : "=r"(r0), "=r"(r1), "=r"(r2), "=r"(r3) : "r"(addr));
}

// int8 IMMA: m16n8k32, s32 accumulate
__device__ __forceinline__ void mma_s8(int* c, const uint32_t* a, const uint32_t* b) {
    asm volatile(
        "mma.sync.aligned.m16n8k32.row.col.s32.s8.s8.s32 "
        "{%0,%1,%2,%3}, {%4,%5,%6,%7}, {%8,%9}, {%0,%1,%2,%3};"
        : "+r"(c[0]), "+r"(c[1]), "+r"(c[2]), "+r"(c[3])
        : "r"(a[0]), "r"(a[1]), "r"(a[2]), "r"(a[3]), "r"(b[0]), "r"(b[1]));
}

// ---------------------------------------------------------------------------
// Kernel 0: fp32 -> int8 per-row symmetric quantization, tiled into 16KB
// SW128-swizzled blocks. One warp per row (1024 floats); lane covers 32
// consecutive cols (two 16B output groups). Stores inv scale = max/127.
// blk = tile*tileStride + kc*kcStride   (A: 8,1   B: 1,16)
// ---------------------------------------------------------------------------
__global__ __launch_bounds__(256)
void quant_kernel(const float* __restrict__ src,
                  uint4* __restrict__ dst, float* __restrict__ inv_scale,
                  int tileStride, int kcStride)
{
    const int warp = threadIdx.x >> 5;
    const int lane = threadIdx.x & 31;
    const int row = blockIdx.x * 8 + warp;

    const float* rp = src + (size_t)row * D_DIM + lane * 32;
    float x[32];
#pragma unroll
    for (int i = 0; i < 8; ++i) {
        float4 v = *(const float4*)(rp + i * 4);
        x[4*i+0] = v.x; x[4*i+1] = v.y; x[4*i+2] = v.z; x[4*i+3] = v.w;
    }
    float m = fabsf(x[0]);
#pragma unroll
    for (int i = 1; i < 32; ++i) m = fmaxf(m, fabsf(x[i]));
#pragma unroll
    for (int off = 16; off > 0; off >>= 1)
        m = fmaxf(m, __shfl_xor_sync(0xffffffffu, m, off));

    const float scale = 127.0f / m;
    if (lane == 0) inv_scale[row] = m * (1.0f / 127.0f);

    const int tile = row >> 7;
    const int r = row & 127;
#pragma unroll
    for (int j = 0; j < 2; ++j) {
        uint32_t w[4];
#pragma unroll
        for (int g = 0; g < 4; ++g) {
            int q0 = __float2int_rn(x[16*j + 4*g + 0] * scale);
            int q1 = __float2int_rn(x[16*j + 4*g + 1] * scale);
            int q2 = __float2int_rn(x[16*j + 4*g + 2] * scale);
            int q3 = __float2int_rn(x[16*j + 4*g + 3] * scale);
            w[g] = (uint32_t)(q0 & 0xff) | ((uint32_t)(q1 & 0xff) << 8) |
                   ((uint32_t)(q2 & 0xff) << 16) | ((uint32_t)q3 << 24);
        }
        const int byteoff = lane * 32 + j * 16;
        const int kc = byteoff >> 7;
        uint32_t o = r * 128 + (byteoff & 127);
        o ^= (o >> 3) & 0x70;                     // SW128 swizzle
        const size_t blk = (size_t)tile * tileStride + (size_t)kc * kcStride;
        dst[blk * 1024 + (o >> 4)] = make_uint4(w[0], w[1], w[2], w[3]);
    }
}

// ---------------------------------------------------------------------------
// Kernel 1: int8 GEMM via mma.sync m16n8k32:  C(bf16) ~= (Aq*inva)·(Bq*invb)^T
// CTA tile 128(M) x 128(N), BK=128 int8; 8 stages (one per k-chunk).
// 4 warps (128 thr), warp tile 64x64 (4 m-frags x 8 n-frags, 128 s32 acc).
// 3-stage pipeline (96KB smem), 2 CTAs/SM. Epilogue dequantizes with the
// per-row scales and stores bf16.
// ---------------------------------------------------------------------------
#define G_STAGE_BYTES 32768
#define G_SMEM_TOTAL  (3 * G_STAGE_BYTES)   // 98304

__device__ __forceinline__ void gemm_copy_stage(
    uint32_t sbuf, int kc, int mt, int nt, int tid,
    const uint8_t* Aq, const uint8_t* Bq)
{
    const uint8_t* ASrc = Aq + ((size_t)(mt * 8 + kc)) * 16384;
    const uint8_t* BSrc = Bq + ((size_t)(kc * 16 + nt)) * 16384;
#pragma unroll
    for (int i = 0; i < 8; ++i) {
        const int ch = tid + i * 128;
        cp_async16(sbuf + ch * 16,          ASrc + (size_t)ch * 16);
        cp_async16(sbuf + 16384 + ch * 16,  BSrc + (size_t)ch * 16);
    }
    cp_commit();
}

__global__ __launch_bounds__(128, 2)
void gemm_s8_mma_kernel(const uint8_t* __restrict__ Aq,
                        const uint8_t* __restrict__ Bq,
                        const float* __restrict__ inva,
                        const float* __restrict__ invb,
                        __nv_bfloat16* __restrict__ C)
{
    extern __shared__ char smem[];
    const uint32_t sb = smem_to_u32(smem);
    const int tid = threadIdx.x;
    const int wid = tid >> 5;
    const int lane = tid & 31;
    const int nt = blockIdx.x;   // 0..15  (N tile of 128)  -- fastest: A reuse in L2
    const int mt = blockIdx.y;   // 0..255 (M tile of 128)

    const int wm = (wid >> 1) * 64;   // warp m offset (0 or 64)
    const int wn = (wid & 1) * 64;    // warp n offset (0 or 64)

    int acc[4][8][4];
#pragma unroll
    for (int i = 0; i < 4; ++i)
#pragma unroll
        for (int j = 0; j < 8; ++j)
#pragma unroll
            for (int r = 0; r < 4; ++r) acc[i][j][r] = 0;

    gemm_copy_stage(sb + 0 * G_STAGE_BYTES, 0, mt, nt, tid, Aq, Bq);
    gemm_copy_stage(sb + 1 * G_STAGE_BYTES, 1, mt, nt, tid, Aq, Bq);
    gemm_copy_stage(sb + 2 * G_STAGE_BYTES, 2, mt, nt, tid, Aq, Bq);

    const int lrow15 = lane & 15;
    const int lhalf  = lane >> 4;

    for (int it = 0; it < 8; ++it) {
        if (it < 6)       cp_wait<2>();
        else if (it == 6) cp_wait<1>();
        else              cp_wait<0>();
        __syncthreads();

        const uint32_t aBase = sb + (uint32_t)(it % 3) * G_STAGE_BYTES;
        const uint32_t bBase = aBase + 16384;

        // kk selects a 32-byte k-window (two 16B units); unit = 2*kk + lhalf
#pragma unroll
        for (int kk = 0; kk < 4; ++kk) {
            const int unit = 2 * kk + lhalf;
            uint32_t a[4][4];
            uint32_t b[8][2];
#pragma unroll
            for (int mi = 0; mi < 4; ++mi) {
                const int row = wm + mi * 16 + lrow15;
                ldmatrix_x4(a[mi][0], a[mi][1], a[mi][2], a[mi][3],
                            aBase + row * 128 + ((unit ^ (row & 7)) << 4));
            }
#pragma unroll
            for (int j = 0; j < 4; ++j) {
                const int row = wn + j * 16 + lrow15;
                uint32_t r0, r1, r2, r3;
                ldmatrix_x4(r0, r1, r2, r3,
                            bBase + row * 128 + ((unit ^ (row & 7)) << 4));
                b[2*j][0]   = r0; b[2*j][1]   = r2;
                b[2*j+1][0] = r1; b[2*j+1][1] = r3;
            }
#pragma unroll
            for (int mi = 0; mi < 4; ++mi)
#pragma unroll
                for (int ni = 0; ni < 8; ++ni)
                    mma_s8(acc[mi][ni], a[mi], b[ni]);
        }

        __syncthreads();
        if (it + 3 < 8)
            gemm_copy_stage(sb + (uint32_t)((it + 3) % 3) * G_STAGE_BYTES,
                            it + 3, mt, nt, tid, Aq, Bq);
    }

    // epilogue: dequantize (per-row x per-col scales), pack bf16x2
    const int rbase = mt * 128 + wm + (lane >> 2);
    const int cbase = nt * 128 + wn + 2 * (lane & 3);
#pragma unroll
    for (int mi = 0; mi < 4; ++mi) {
        const int r0 = rbase + mi * 16;
        const float ia0 = inva[r0];
        const float ia1 = inva[r0 + 8];
#pragma unroll
        for (int ni = 0; ni < 8; ++ni) {
            const int c0 = cbase + ni * 8;
            const float s0 = invb[c0];
            const float s1 = invb[c0 + 1];
            float l00 = __int2float_rn(acc[mi][ni][0]) * ia0 * s0;
            float l01 = __int2float_rn(acc[mi][ni][1]) * ia0 * s1;
            float l10 = __int2float_rn(acc[mi][ni][2]) * ia1 * s0;
            float l11 = __int2float_rn(acc[mi][ni][3]) * ia1 * s1;
            uint32_t w0 = (uint32_t)__bfloat16_as_ushort(__float2bfloat16_rn(l00))
                        | ((uint32_t)__bfloat16_as_ushort(__float2bfloat16_rn(l01)) << 16);
            uint32_t w1 = (uint32_t)__bfloat16_as_ushort(__float2bfloat16_rn(l10))
                        | ((uint32_t)__bfloat16_as_ushort(__float2bfloat16_rn(l11)) << 16);
            *(uint32_t*)(C + (size_t)r0 * K_CODE + c0)       = w0;
            *(uint32_t*)(C + (size_t)(r0 + 8) * K_CODE + c0) = w1;
        }
    }
}

// ---------------------------------------------------------------------------
// fast 2^y (degree-4 poly after round-to-nearest split; rel err ~4e-5).
// ---------------------------------------------------------------------------
__device__ __forceinline__ float fast_exp2(float y)
{
    float r = rintf(y);
    float f = y - r;
    float p = 9.6181291e-3f;
    p = fmaf(p, f, 5.5504109e-2f);
    p = fmaf(p, f, 2.4022651e-1f);
    p = fmaf(p, f, 6.9314718e-1f);
    p = fmaf(p, f, 1.0f);
    int ei = (int)r;
    if (ei < -126) return 0.f;
    float s = __int_as_float((ei + 127) << 23);
    return p * s;
}

// ---------------------------------------------------------------------------
// Kernel 2: row pass over bf16 logits, warp-per-token (no block syncs).
// Candidate threshold 4.0 covers the int8 GEMM + bf16-store logit error.
// col(j) = 8*lane + 256*(j>>3) + (j&7)
// ---------------------------------------------------------------------------
__global__ __launch_bounds__(256)
void row_pass_kernel(const __nv_bfloat16* __restrict__ S)
{
    const int lane = threadIdx.x & 31;
    const int warp = threadIdx.x >> 5;
    const int gw = blockIdx.x * 8 + warp;        // global warp id, 0..4095

    float dreg[64];
#pragma unroll
    for (int j = 0; j < 64; ++j) dreg[j] = 0.f;
    float hsum = 0.f;

    for (int t = 0; t < 8; ++t) {
        const int tok = gw * 8 + t;
        const uint4* row4 = (const uint4*)(S + (size_t)tok * K_CODE);

        float v[64];
#pragma unroll
        for (int jj = 0; jj < 8; ++jj) {
            uint4 x = row4[lane + 32 * jj];
            const uint32_t w[4] = {x.x, x.y, x.z, x.w};
#pragma unroll
            for (int wi = 0; wi < 4; ++wi) {
                v[jj*8 + 2*wi + 0] = __uint_as_float(w[wi] << 16);
                v[jj*8 + 2*wi + 1] = __uint_as_float(w[wi] & 0xffff0000u);
            }
        }

        // ---- max (warp) ----
        float m = v[0];
#pragma unroll
        for (int j = 1; j < 64; ++j) m = fmaxf(m, v[j]);
#pragma unroll
        for (int off = 16; off > 0; off >>= 1)
            m = fmaxf(m, __shfl_xor_sync(0xffffffffu, m, off));

        // ---- candidates within 4.0 of max ----
        const float thr = m - 4.0f;
        int cnt_l = 0;
#pragma unroll
        for (int j = 0; j < 64; ++j) cnt_l += (v[j] >= thr) ? 1 : 0;
        int pre = cnt_l;
#pragma unroll
        for (int off = 1; off < 32; off <<= 1) {
            int n = __shfl_up_sync(0xffffffffu, pre, off);
            if (lane >= off) pre += n;
        }
        const int total = __shfl_sync(0xffffffffu, pre, 31);
        int slot = pre - cnt_l;   // exclusive prefix
        if (cnt_l) {
#pragma unroll
            for (int j = 0; j < 64; ++j) {
                if (v[j] >= thr) {
                    if (slot < NCAND)
                        g_cand_idx[tok][slot] = 8 * lane + 256 * (j >> 3) + (j & 7);
                    ++slot;
                }
            }
        }
        if (lane == 0) g_cand_cnt[tok] = (total < NCAND) ? total : NCAND;

        // ---- softmax stats ----
        const float LOG2E = 1.4426950408889634f;
        float s0 = 0.f, s1 = 0.f;
#pragma unroll
        for (int j = 0; j < 64; ++j) {
            float y = (v[j] - m) * LOG2E;
            float e = fast_exp2(y);
            v[j] = e;
            s0 += e;
            s1 = fmaf(e, y, s1);
        }
#pragma unroll
        for (int off = 16; off > 0; off >>= 1) {
            s0 += __shfl_xor_sync(0xffffffffu, s0, off);
            s1 += __shfl_xor_sync(0xffffffffu, s1, off);
        }
        const float inv = 1.f / s0;
#pragma unroll
        for (int j = 0; j < 64; ++j) dreg[j] = fmaf(v[j], inv, dreg[j]);
        hsum += s1 * inv - log2f(s0);
    }

    // per-warp diversity partial; dreg[jj*8+e] -> col 8*lane + 256*jj + e
    float4* dp = (float4*)(g_div_part + (size_t)gw * K_CODE);
#pragma unroll
    for (int jj = 0; jj < 8; ++jj) {
        dp[2*lane + 64*jj]     = make_float4(dreg[jj*8+0], dreg[jj*8+1], dreg[jj*8+2], dreg[jj*8+3]);
        dp[2*lane + 64*jj + 1] = make_float4(dreg[jj*8+4], dreg[jj*8+5], dreg[jj*8+6], dreg[jj*8+7]);
    }
    if (lane == 0) g_h_part[gw] = hsum;
}

// ---------------------------------------------------------------------------
// Kernel 2b: fp64 refinement of argmax among candidates (1 warp/token).
// ---------------------------------------------------------------------------
__global__ __launch_bounds__(256)
void refine_kernel(const float* __restrict__ inputs,
                   const float* __restrict__ codebook,
                   float* __restrict__ nn_out)
{
    const int warp = threadIdx.x >> 5;
    const int lane = threadIdx.x & 31;
    const int tok = blockIdx.x * 8 + warp;

    const int cnt = g_cand_cnt[tok];
    int best = g_cand_idx[tok][0];

    if (cnt > 1) {
        const float* xr = inputs + (size_t)tok * D_DIM;
        double bv = -1e300;
        int bi = INT_MAX;
        for (int c = 0; c < cnt; ++c) {
            const int idx = g_cand_idx[tok][c];
            const float* cr = codebook + (size_t)idx * D_DIM;
            double s = 0.0;
            for (int i = lane; i < D_DIM; i += 32)
                s += (double)xr[i] * (double)cr[i];
#pragma unroll
            for (int off = 16; off > 0; off >>= 1)
                s += __shfl_down_sync(0xffffffffu, s, off);
            s = __shfl_sync(0xffffffffu, s, 0);
            if (s > bv || (s == bv && idx < bi)) { bv = s; bi = idx; }
        }
        best = bi;
    }

    if (lane == 0) {
        g_nn[tok] = best;
        nn_out[tok] = (float)best;
    }
}

// ---------------------------------------------------------------------------
// Kernel 3a: diversity reduce across the 4096 per-warp partials (16 CTAs).
// ---------------------------------------------------------------------------
__global__ __launch_bounds__(128)
void div_reduce_kernel()
{
    const int col = blockIdx.x * 128 + threadIdx.x;
    float s = 0.f;
#pragma unroll 8
    for (int w = 0; w < RP_WARPS; ++w)
        s += g_div_part[(size_t)w * K_CODE + col];
    float dv = s * (1.f / (float)M_TOK);
    float acc = dv * log2f(dv + 1e-8f);

    __shared__ float sa[128];
    sa[threadIdx.x] = acc;
    __syncthreads();
    for (int off = 64; off > 0; off >>= 1) {
        if (threadIdx.x < off) sa[threadIdx.x] += sa[threadIdx.x + off];
        __syncthreads();
    }
    if (threadIdx.x == 0) g_acc_part[blockIdx.x] = sa[0];
}

// ---------------------------------------------------------------------------
// Kernel 3b: final scalar loss.
// ---------------------------------------------------------------------------
__global__ __launch_bounds__(256)
void finalize2_kernel()
{
    const int tid = threadIdx.x;
    float h = 0.f;
#pragma unroll
    for (int i = 0; i < RP_WARPS / 256; ++i)     // 16 per thread
        h += g_h_part[tid * (RP_WARPS / 256) + i];
    float a = (tid < 16) ? g_acc_part[tid] : 0.f;

    __shared__ float sh[256], sa[256];
    sh[tid] = h; sa[tid] = a;
    __syncthreads();
    for (int off = 128; off > 0; off >>= 1) {
        if (tid < off) { sh[tid] += sh[tid + off]; sa[tid] += sa[tid + off]; }
        __syncthreads();
    }
    if (tid == 0) {
        float h_clust = -sh[0] / (float)M_TOK;
        g_loss[0] = h_clust + sa[0];   // loss = h_clust - (-sa) = h_clust + sa
    }
}

// ---------------------------------------------------------------------------
// Kernel 4: broadcast scalar loss into the qloss region.
// ---------------------------------------------------------------------------
__global__ __launch_bounds__(256)
void fill_loss_kernel(float* __restrict__ dst)
{
    const float v = g_loss[0];
    const float4 v4 = make_float4(v, v, v, v);
    size_t i = ((size_t)blockIdx.x * blockDim.x + threadIdx.x);
    const size_t stride = (size_t)gridDim.x * blockDim.x;
    const size_t n4 = LOSS_N / 4;
    float4* d4 = (float4*)dst;
    for (; i < n4; i += stride) d4[i] = v4;
}

// ---------------------------------------------------------------------------
// Kernel 5: copy codebook into output.
// ---------------------------------------------------------------------------
__global__ __launch_bounds__(256)
void copy_cb_kernel(const float* __restrict__ src, float* __restrict__ dst)
{
    size_t i = ((size_t)blockIdx.x * blockDim.x + threadIdx.x);
    const size_t stride = (size_t)gridDim.x * blockDim.x;
    const size_t n4 = CB_N / 4;
    const float4* s4 = (const float4*)src;
    float4* d4 = (float4*)dst;
    for (; i < n4; i += stride) d4[i] = s4[i];
}

// ---------------------------------------------------------------------------
// Kernel 6: gather + center + L2-normalize + straight-through identity.
// ---------------------------------------------------------------------------
__global__ __launch_bounds__(256)
void quantize_kernel(const float* __restrict__ inputs,
                     const float* __restrict__ codebook,
                     float* __restrict__ qout)
{
    const int warp = threadIdx.x >> 5;
    const int lane = threadIdx.x & 31;
    const int tok = blockIdx.x * 8 + warp;
    const int idx = g_nn[tok];
    const float* row = codebook + (size_t)idx * D_DIM;

    float4 x[8];
    float sum = 0.f;
#pragma unroll
    for (int c = 0; c < 8; ++c) {
        x[c] = *(const float4*)(row + c * 128 + lane * 4);
        sum += x[c].x + x[c].y + x[c].z + x[c].w;
    }
#pragma unroll
    for (int off = 16; off > 0; off >>= 1)
        sum += __shfl_xor_sync(0xffffffffu, sum, off);
    const float mean = sum * (1.f / (float)D_DIM);

    float ss = 0.f;
#pragma unroll
    for (int c = 0; c < 8; ++c) {
        x[c].x -= mean; x[c].y -= mean; x[c].z -= mean; x[c].w -= mean;
        ss += x[c].x * x[c].x + x[c].y * x[c].y + x[c].z * x[c].z + x[c].w * x[c].w;
    }
#pragma unroll
    for (int off = 16; off > 0; off >>= 1)
        ss += __shfl_xor_sync(0xffffffffu, ss, off);
    const float invn = 1.f / sqrtf(ss);

    const float* xin = inputs + (size_t)tok * D_DIM;
    float* out = qout + (size_t)tok * D_DIM;
#pragma unroll
    for (int c = 0; c < 8; ++c) {
        float4 iv = *(const float4*)(xin + c * 128 + lane * 4);
        float4 v;
        v.x = iv.x + (x[c].x * invn - iv.x);
        v.y = iv.y + (x[c].y * invn - iv.y);
        v.z = iv.z + (x[c].z * invn - iv.z);
        v.w = iv.w + (x[c].w * invn - iv.w);
        *(float4*)(out + c * 128 + lane * 4) = v;
    }
}

// ---------------------------------------------------------------------------
extern "C" void kernel_launch(void* const* d_in, const int* in_sizes, int n_in,
                              void* d_out, int out_size)
{
    const float* inputs   = (const float*)d_in[0];
    const float* codebook = (const float*)d_in[1];
    float* out = (float*)d_out;

    __nv_bfloat16 *logits;
    uint4 *Aq, *Bq;
    float *inva, *invb;
    cudaGetSymbolAddress((void**)&logits, g_logits);
    cudaGetSymbolAddress((void**)&Aq, g_Aq);
    cudaGetSymbolAddress((void**)&Bq, g_Bq);
    cudaGetSymbolAddress((void**)&inva, g_inva);
    cudaGetSymbolAddress((void**)&invb, g_invb);

    // 0) per-row int8 quantization, pre-tiled + swizzled
    quant_kernel<<<M_TOK / 8, 256>>>(inputs, Aq, inva, 8, 1);
    quant_kernel<<<K_CODE / 8, 256>>>(codebook, Bq, invb, 1, 16);

    // 1) int8 similarity GEMM (IMMA m16n8k32), 64x64 warp tiles, 2 CTA/SM
    cudaFuncSetAttribute(gemm_s8_mma_kernel,
                         cudaFuncAttributeMaxDynamicSharedMemorySize, G_SMEM_TOTAL);
    {
        dim3 grid(K_CODE / 128, M_TOK / 128);   // (16, 256), nt fastest
        gemm_s8_mma_kernel<<<grid, 128, G_SMEM_TOTAL>>>(
            (const uint8_t*)Aq, (const uint8_t*)Bq, inva, invb, logits);
    }

    // 2) row pass (warp-per-token, bf16 logits)
    row_pass_kernel<<<RP_WARPS / 8, 256>>>(logits);
    // 2b) fp64 refine of near-tied argmax -> final nn_idx
    refine_kernel<<<M_TOK / 8, 256>>>(inputs, codebook, out + NN_OFF);
    // 3) loss reduction
    div_reduce_kernel<<<16, 128>>>();
    finalize2_kernel<<<1, 256>>>();
    // 4) broadcast loss
    fill_loss_kernel<<<8192, 256>>>(out + LOSS_OFF);
    // 5) codebook passthrough
    copy_cb_kernel<<<2048, 256>>>(codebook, out + CB_OFF);
    // 6) quantized rows
    quantize_kernel<<<M_TOK / 8, 256>>>(inputs, codebook, out + QUANT_OFF);
}

// round 17
// speedup vs baseline: 2.2103x; 2.2103x over previous
#include <cuda_runtime.h>
#include <cuda_bf16.h>
#include <cstdint>
#include <cstddef>
#include <climits>

// ---------------------------------------------------------------------------
// Problem shape (fixed by the dataset)
//   inputs:   [16, 2048, 1024] f32  -> M = 32768 tokens, D = 1024
//   codebook: [2048, 1024]     f32  -> K = 2048 codes
// Outputs concatenated (f32):
//   quantized  [32768,1024]  @ 0
//   qloss      [32768,2048]  @ 33554432   (scalar broadcast)
//   nn_idx     [32768]       @ 100663296  (as float)
//   codebook   [2048,1024]   @ 100696064
// ---------------------------------------------------------------------------
#define M_TOK   32768
#define K_CODE  2048
#define D_DIM   1024

#define QUANT_OFF 0
#define LOSS_OFF  33554432
#define NN_OFF    100663296
#define CB_OFF    100696064
#define LOSS_N    67108864
#define CB_N      2097152

#define NCAND 16

// ------------------------- scratch (device globals) ------------------------
__device__ __nv_bfloat16 g_logits[(size_t)M_TOK * K_CODE];   // 128 MiB (bf16)

#define RP_PAIRS 2048          // 512 CTAs x 4 warp-pairs, 16 tokens per pair
__device__ float g_div_part[(size_t)RP_PAIRS * K_CODE];   // 16 MiB per-pair partials
__device__ float g_h_part[RP_PAIRS];
__device__ float g_acc_part[16];
__device__ int   g_nn[M_TOK];
__device__ float g_loss[1];
__device__ int   g_cand_cnt[M_TOK];
__device__ int   g_cand_idx[M_TOK][NCAND];

// bf16 hi operands, pre-tiled + pre-SW128-swizzled into 16KB blocks of
// [128 rows x 64 cols bf16] (= 128 rows x 128B).
//   A blocks ordered [m_tile (256)][k_chunk (16)]
//   B blocks ordered [k_chunk (16)][n_block (16)]
__device__ uint4 g_Ahi[(size_t)M_TOK * D_DIM / 8];   // 64 MiB
__device__ uint4 g_Bhi[(size_t)K_CODE * D_DIM / 8];  // 4 MiB

// ------------------------- PTX helpers ---------------------------
__device__ __forceinline__ uint32_t smem_to_u32(const void* p) {
    uint32_t a;
    asm("{ .reg .u64 t; cvta.to.shared.u64 t, %1; cvt.u32.u64 %0, t; }" : "=r"(a) : "l"(p));
    return a;
}

__device__ __forceinline__ void cp_async16(uint32_t dst, const void* src) {
    asm volatile("cp.async.cg.shared.global [%0], [%1], 16;" :: "r"(dst), "l"(src) : "memory");
}
__device__ __forceinline__ void cp_commit() {
    asm volatile("cp.async.commit_group;" ::: "memory");
}
template <int N>
__device__ __forceinline__ void cp_wait() {
    asm volatile("cp.async.wait_group %0;" :: "n"(N) : "memory");
}

__device__ __forceinline__ void ldmatrix_x4(uint32_t& r0, uint32_t& r1,
                                            uint32_t& r2, uint32_t& r3, uint32_t addr) {
    asm volatile("ldmatrix.sync.aligned.m8n8.x4.shared.b16 {%0,%1,%2,%3}, [%4];"
                 : "=r"(r0), "=r"(r1), "=r"(r2), "=r"(r3) : "r"(addr));
}

__device__ __forceinline__ void mma_bf16(float* c, const uint32_t* a, const uint32_t* b) {
    asm volatile(
        "mma.sync.aligned.m16n8k16.row.col.f32.bf16.bf16.f32 "
        "{%0,%1,%2,%3}, {%4,%5,%6,%7}, {%8,%9}, {%0,%1,%2,%3};"
        : "+f"(c[0]), "+f"(c[1]), "+f"(c[2]), "+f"(c[3])
        : "r"(a[0]), "r"(a[1]), "r"(a[2]), "r"(a[3]), "r"(b[0]), "r"(b[1]));
}

// ---------------------------------------------------------------------------
// Kernel 0: fp32 -> bf16 (hi only), tiled into 16KB SW128-swizzled blocks.
// ---------------------------------------------------------------------------
__global__ __launch_bounds__(256)
void split_kernel(const float* __restrict__ src,
                  uint4* __restrict__ hi,
                  int nchunks, int tileStride, int kcStride)
{
    int i = blockIdx.x * blockDim.x + threadIdx.x;
    if (i >= nchunks) return;
    const int c8   = i & 127;
    const int row  = i >> 7;
    const int kc   = c8 >> 3;
    const int g    = c8 & 7;
    const int tile = row >> 7;
    const int r    = row & 127;

    const size_t blk = (size_t)tile * tileStride + (size_t)kc * kcStride;
    uint32_t off = r * 128 + g * 16;
    off ^= (off >> 3) & 0x70;                     // SW128 swizzle
    const size_t dst = blk * 1024 + (off >> 4);

    const float4* s4 = (const float4*)(src + ((size_t)row << 10) + (c8 << 3));
    float4 x0 = s4[0], x1 = s4[1];
    float xs[8] = {x0.x, x0.y, x0.z, x0.w, x1.x, x1.y, x1.z, x1.w};
    uint32_t hw[4];
#pragma unroll
    for (int j = 0; j < 4; ++j) {
        __nv_bfloat16 h0 = __float2bfloat16_rn(xs[2*j]);
        __nv_bfloat16 h1 = __float2bfloat16_rn(xs[2*j+1]);
        hw[j] = (uint32_t)__bfloat16_as_ushort(h0) | ((uint32_t)__bfloat16_as_ushort(h1) << 16);
    }
    hi[dst] = make_uint4(hw[0], hw[1], hw[2], hw[3]);
}

// ---------------------------------------------------------------------------
// Kernel 1: single-split bf16 GEMM via mma.sync:  C(bf16) ~= Ahi * Bhi^T.
// (Reverted from INT8 IMMA: legacy int8 mma.sync runs ~4x slower than bf16
//  on sm_103a's compatibility tensor path — measured R16.)
// CTA tile 128x128, BK=64; 16 stages; 4 warps, warp tile 64x64;
// 3-stage cp.async pipeline (96KB smem), 2 CTAs/SM; bf16 C stores.
// ---------------------------------------------------------------------------
#define G_STAGE_BYTES 32768
#define G_SMEM_TOTAL  (3 * G_STAGE_BYTES)   // 98304

__device__ __forceinline__ void gemm_copy_stage(
    uint32_t sbuf, int kc, int mt, int nt, int tid,
    const uint8_t* Ahi, const uint8_t* Bhi)
{
    const uint8_t* ASrc = Ahi + ((size_t)(mt * 16 + kc)) * 16384;
    const uint8_t* BSrc = Bhi + ((size_t)(kc * 16 + nt)) * 16384;
#pragma unroll
    for (int i = 0; i < 8; ++i) {
        const int ch = tid + i * 128;
        cp_async16(sbuf + ch * 16,          ASrc + (size_t)ch * 16);
        cp_async16(sbuf + 16384 + ch * 16,  BSrc + (size_t)ch * 16);
    }
    cp_commit();
}

__global__ __launch_bounds__(128, 2)
void gemm_bf16x1_mma_kernel(const uint8_t* __restrict__ Ahi,
                            const uint8_t* __restrict__ Bhi,
                            __nv_bfloat16* __restrict__ C)
{
    extern __shared__ char smem[];
    const uint32_t sb = smem_to_u32(smem);
    const int tid = threadIdx.x;
    const int wid = tid >> 5;
    const int lane = tid & 31;
    const int nt = blockIdx.x;   // 0..15  (N tile of 128)  -- fastest: A reuse in L2
    const int mt = blockIdx.y;   // 0..255 (M tile of 128)

    const int wm = (wid >> 1) * 64;   // warp m offset (0 or 64)
    const int wn = (wid & 1) * 64;    // warp n offset (0 or 64)

    float acc[4][8][4];
#pragma unroll
    for (int i = 0; i < 4; ++i)
#pragma unroll
        for (int j = 0; j < 8; ++j)
#pragma unroll
            for (int r = 0; r < 4; ++r) acc[i][j][r] = 0.f;

    gemm_copy_stage(sb + 0 * G_STAGE_BYTES, 0, mt, nt, tid, Ahi, Bhi);
    gemm_copy_stage(sb + 1 * G_STAGE_BYTES, 1, mt, nt, tid, Ahi, Bhi);
    gemm_copy_stage(sb + 2 * G_STAGE_BYTES, 2, mt, nt, tid, Ahi, Bhi);

    const int lrow15 = lane & 15;
    const int lhalf  = lane >> 4;

    for (int it = 0; it < 16; ++it) {
        if (it < 14)       cp_wait<2>();
        else if (it == 14) cp_wait<1>();
        else               cp_wait<0>();
        __syncthreads();

        const uint32_t aBase = sb + (uint32_t)(it % 3) * G_STAGE_BYTES;
        const uint32_t bBase = aBase + 16384;

#pragma unroll
        for (int kk = 0; kk < 4; ++kk) {
            const int unit = 2 * kk + lhalf;
            uint32_t a[4][4];
            uint32_t b[8][2];
#pragma unroll
            for (int mi = 0; mi < 4; ++mi) {
                const int row = wm + mi * 16 + lrow15;
                ldmatrix_x4(a[mi][0], a[mi][1], a[mi][2], a[mi][3],
                            aBase + row * 128 + ((unit ^ (row & 7)) << 4));
            }
#pragma unroll
            for (int j = 0; j < 4; ++j) {
                const int row = wn + j * 16 + lrow15;
                uint32_t r0, r1, r2, r3;
                ldmatrix_x4(r0, r1, r2, r3,
                            bBase + row * 128 + ((unit ^ (row & 7)) << 4));
                b[2*j][0]   = r0; b[2*j][1]   = r2;
                b[2*j+1][0] = r1; b[2*j+1][1] = r3;
            }
#pragma unroll
            for (int mi = 0; mi < 4; ++mi)
#pragma unroll
                for (int ni = 0; ni < 8; ++ni)
                    mma_bf16(acc[mi][ni], a[mi], b[ni]);
        }

        __syncthreads();
        if (it + 3 < 16)
            gemm_copy_stage(sb + (uint32_t)((it + 3) % 3) * G_STAGE_BYTES,
                            it + 3, mt, nt, tid, Ahi, Bhi);
    }

    // epilogue: pack pairs of fp32 acc into bf16x2 words
    const int rbase = mt * 128 + wm + (lane >> 2);
    const int cbase = nt * 128 + wn + 2 * (lane & 3);
#pragma unroll
    for (int mi = 0; mi < 4; ++mi) {
#pragma unroll
        for (int ni = 0; ni < 8; ++ni) {
            const int r0 = rbase + mi * 16;
            const int c0 = cbase + ni * 8;
            uint32_t w0 = (uint32_t)__bfloat16_as_ushort(__float2bfloat16_rn(acc[mi][ni][0]))
                        | ((uint32_t)__bfloat16_as_ushort(__float2bfloat16_rn(acc[mi][ni][1])) << 16);
            uint32_t w1 = (uint32_t)__bfloat16_as_ushort(__float2bfloat16_rn(acc[mi][ni][2]))
                        | ((uint32_t)__bfloat16_as_ushort(__float2bfloat16_rn(acc[mi][ni][3])) << 16);
            *(uint32_t*)(C + (size_t)r0 * K_CODE + c0)       = w0;
            *(uint32_t*)(C + (size_t)(r0 + 8) * K_CODE + c0) = w1;
        }
    }
}

// ---------------------------------------------------------------------------
// fast 2^y (degree-4 poly after round-to-nearest split; rel err ~4e-5).
// ---------------------------------------------------------------------------
__device__ __forceinline__ float fast_exp2(float y)
{
    float r = rintf(y);
    float f = y - r;
    float p = 9.6181291e-3f;
    p = fmaf(p, f, 5.5504109e-2f);
    p = fmaf(p, f, 2.4022651e-1f);
    p = fmaf(p, f, 6.9314718e-1f);
    p = fmaf(p, f, 1.0f);
    int ei = (int)r;
    if (ei < -126) return 0.f;
    float s = __int_as_float((ei + 127) << 23);
    return p * s;
}

// ---------------------------------------------------------------------------
// Kernel 2: row pass, WARP-PAIR per token.
// 512 CTAs x 8 warps = 4 pairs/CTA, 16 tokens per pair. Each warp holds half
// a row (32 logits/lane) + half the diversity accumulator (32 regs), cutting
// registers from ~247 to ~100 -> 2 CTAs/SM (double occupancy).
// Cross-warp exchange via per-pair smem slots + bar.sync(pairid, 64),
// double-buffered by token parity (2 barriers per token).
// Candidates recorded in a bitmask before exp overwrites v.
// col(ph, lane, j) = ph*1024 + 8*lane + 256*(j>>3) + (j&7)
// ---------------------------------------------------------------------------
__global__ __launch_bounds__(256, 2)
void row_pass_kernel(const __nv_bfloat16* __restrict__ S)
{
    const int lane = threadIdx.x & 31;
    const int warp = threadIdx.x >> 5;
    const int pairid = warp >> 1;            // 0..3
    const int ph = warp & 1;                 // which half of the row
    const int pairg = blockIdx.x * 4 + pairid;   // 0..2047

    __shared__ float s_max[4][2][2];
    __shared__ float s_s0[4][2][2], s_s1[4][2][2];
    __shared__ int   s_cnt[4][2][2];

    float dreg[32];
#pragma unroll
    for (int j = 0; j < 32; ++j) dreg[j] = 0.f;
    float hsum = 0.f;

    for (int t = 0; t < 16; ++t) {
        const int tok = pairg * 16 + t;
        const int par = t & 1;
        const uint4* row4 = (const uint4*)(S + (size_t)tok * K_CODE) + ph * 128;

        float v[32];
#pragma unroll
        for (int jj = 0; jj < 4; ++jj) {
            uint4 x = row4[lane + 32 * jj];
            const uint32_t w[4] = {x.x, x.y, x.z, x.w};
#pragma unroll
            for (int wi = 0; wi < 4; ++wi) {
                v[jj*8 + 2*wi + 0] = __uint_as_float(w[wi] << 16);
                v[jj*8 + 2*wi + 1] = __uint_as_float(w[wi] & 0xffff0000u);
            }
        }

        // ---- local + warp max, exchange across the pair ----
        float m = v[0];
#pragma unroll
        for (int j = 1; j < 32; ++j) m = fmaxf(m, v[j]);
#pragma unroll
        for (int off = 16; off > 0; off >>= 1)
            m = fmaxf(m, __shfl_xor_sync(0xffffffffu, m, off));
        if (lane == 0) s_max[pairid][par][ph] = m;
        asm volatile("bar.sync %0, %1;" :: "r"(pairid), "r"(64) : "memory");
        m = fmaxf(s_max[pairid][par][0], s_max[pairid][par][1]);

        // ---- candidate mask (before exp overwrites v) ----
        const float thr = m - 1.25f;
        uint32_t cmask = 0;
#pragma unroll
        for (int j = 0; j < 32; ++j)
            cmask |= (v[j] >= thr) ? (1u << j) : 0u;
        const int cnt_l = __popc(cmask);
        int pre = cnt_l;
#pragma unroll
        for (int off = 1; off < 32; off <<= 1) {
            int n = __shfl_up_sync(0xffffffffu, pre, off);
            if (lane >= off) pre += n;
        }
        const int wtotal = __shfl_sync(0xffffffffu, pre, 31);

        // ---- exp + sums (overwrites v with e) ----
        const float LOG2E = 1.4426950408889634f;
        float s0 = 0.f, s1 = 0.f;
#pragma unroll
        for (int j = 0; j < 32; ++j) {
            float y = (v[j] - m) * LOG2E;
            float e = fast_exp2(y);
            v[j] = e;
            s0 += e;
            s1 = fmaf(e, y, s1);
        }
#pragma unroll
        for (int off = 16; off > 0; off >>= 1) {
            s0 += __shfl_xor_sync(0xffffffffu, s0, off);
            s1 += __shfl_xor_sync(0xffffffffu, s1, off);
        }
        if (lane == 0) {
            s_s0[pairid][par][ph] = s0;
            s_s1[pairid][par][ph] = s1;
            s_cnt[pairid][par][ph] = wtotal;
        }
        asm volatile("bar.sync %0, %1;" :: "r"(pairid), "r"(64) : "memory");

        const float S0 = s_s0[pairid][par][0] + s_s0[pairid][par][1];
        const float S1 = s_s1[pairid][par][0] + s_s1[pairid][par][1];
        const int cnt0 = s_cnt[pairid][par][0];
        const int cnt1 = s_cnt[pairid][par][1];
        const float inv = 1.f / S0;

        // ---- write candidates (warp0 slots [0,cnt0), warp1 after) ----
        int slot = (ph ? cnt0 : 0) + pre - cnt_l;
        if (cmask) {
#pragma unroll
            for (int j = 0; j < 32; ++j) {
                if ((cmask >> j) & 1u) {
                    if (slot < NCAND)
                        g_cand_idx[tok][slot] = ph * 1024 + 8 * lane + 256 * (j >> 3) + (j & 7);
                    ++slot;
                }
            }
        }
        if (ph == 0 && lane == 0) {
            const int total = cnt0 + cnt1;
            g_cand_cnt[tok] = (total < NCAND) ? total : NCAND;
            hsum += S1 * inv - log2f(S0);
        }

        // ---- diversity accumulation ----
#pragma unroll
        for (int j = 0; j < 32; ++j) dreg[j] = fmaf(v[j], inv, dreg[j]);
    }

    // per-pair diversity partial; dreg[jj*8+e] -> local col 8*lane+256*jj+e
    float4* dp = (float4*)(g_div_part + (size_t)pairg * K_CODE + ph * 1024);
#pragma unroll
    for (int jj = 0; jj < 4; ++jj) {
        dp[2*lane + 64*jj]     = make_float4(dreg[jj*8+0], dreg[jj*8+1], dreg[jj*8+2], dreg[jj*8+3]);
        dp[2*lane + 64*jj + 1] = make_float4(dreg[jj*8+4], dreg[jj*8+5], dreg[jj*8+6], dreg[jj*8+7]);
    }
    if (ph == 0 && lane == 0) g_h_part[pairg] = hsum;
}

// ---------------------------------------------------------------------------
// Kernel 2b: fp64 refinement of argmax among candidates (1 warp/token).
// ---------------------------------------------------------------------------
__global__ __launch_bounds__(256)
void refine_kernel(const float* __restrict__ inputs,
                   const float* __restrict__ codebook,
                   float* __restrict__ nn_out)
{
    const int warp = threadIdx.x >> 5;
    const int lane = threadIdx.x & 31;
    const int tok = blockIdx.x * 8 + warp;

    const int cnt = g_cand_cnt[tok];
    int best = g_cand_idx[tok][0];

    if (cnt > 1) {
        const float* xr = inputs + (size_t)tok * D_DIM;
        double bv = -1e300;
        int bi = INT_MAX;
        for (int c = 0; c < cnt; ++c) {
            const int idx = g_cand_idx[tok][c];
            const float* cr = codebook + (size_t)idx * D_DIM;
            double s = 0.0;
            for (int i = lane; i < D_DIM; i += 32)
                s += (double)xr[i] * (double)cr[i];
#pragma unroll
            for (int off = 16; off > 0; off >>= 1)
                s += __shfl_down_sync(0xffffffffu, s, off);
            s = __shfl_sync(0xffffffffu, s, 0);
            if (s > bv || (s == bv && idx < bi)) { bv = s; bi = idx; }
        }
        best = bi;
    }

    if (lane == 0) {
        g_nn[tok] = best;
        nn_out[tok] = (float)best;
    }
}

// ---------------------------------------------------------------------------
// Kernel 3a: diversity reduce across the 2048 per-pair partials (16 CTAs).
// ---------------------------------------------------------------------------
__global__ __launch_bounds__(128)
void div_reduce_kernel()
{
    const int col = blockIdx.x * 128 + threadIdx.x;
    float s = 0.f;
#pragma unroll 8
    for (int w = 0; w < RP_PAIRS; ++w)
        s += g_div_part[(size_t)w * K_CODE + col];
    float dv = s * (1.f / (float)M_TOK);
    float acc = dv * log2f(dv + 1e-8f);

    __shared__ float sa[128];
    sa[threadIdx.x] = acc;
    __syncthreads();
    for (int off = 64; off > 0; off >>= 1) {
        if (threadIdx.x < off) sa[threadIdx.x] += sa[threadIdx.x + off];
        __syncthreads();
    }
    if (threadIdx.x == 0) g_acc_part[blockIdx.x] = sa[0];
}

// ---------------------------------------------------------------------------
// Kernel 3b: final scalar loss.
// ---------------------------------------------------------------------------
__global__ __launch_bounds__(256)
void finalize2_kernel()
{
    const int tid = threadIdx.x;
    float h = 0.f;
#pragma unroll
    for (int i = 0; i < RP_PAIRS / 256; ++i)     // 8 per thread
        h += g_h_part[tid * (RP_PAIRS / 256) + i];
    float a = (tid < 16) ? g_acc_part[tid] : 0.f;

    __shared__ float sh[256], sa[256];
    sh[tid] = h; sa[tid] = a;
    __syncthreads();
    for (int off = 128; off > 0; off >>= 1) {
        if (tid < off) { sh[tid] += sh[tid + off]; sa[tid] += sa[tid + off]; }
        __syncthreads();
    }
    if (tid == 0) {
        float h_clust = -sh[0] / (float)M_TOK;
        g_loss[0] = h_clust + sa[0];   // loss = h_clust - (-sa) = h_clust + sa
    }
}

// ---------------------------------------------------------------------------
// Kernel 4: broadcast scalar loss into the qloss region.
// ---------------------------------------------------------------------------
__global__ __launch_bounds__(256)
void fill_loss_kernel(float* __restrict__ dst)
{
    const float v = g_loss[0];
    const float4 v4 = make_float4(v, v, v, v);
    size_t i = ((size_t)blockIdx.x * blockDim.x + threadIdx.x);
    const size_t stride = (size_t)gridDim.x * blockDim.x;
    const size_t n4 = LOSS_N / 4;
    float4* d4 = (float4*)dst;
    for (; i < n4; i += stride) d4[i] = v4;
}

// ---------------------------------------------------------------------------
// Kernel 5: copy codebook into output.
// ---------------------------------------------------------------------------
__global__ __launch_bounds__(256)
void copy_cb_kernel(const float* __restrict__ src, float* __restrict__ dst)
{
    size_t i = ((size_t)blockIdx.x * blockDim.x + threadIdx.x);
    const size_t stride = (size_t)gridDim.x * blockDim.x;
    const size_t n4 = CB_N / 4;
    const float4* s4 = (const float4*)src;
    float4* d4 = (float4*)dst;
    for (; i < n4; i += stride) d4[i] = s4[i];
}

// ---------------------------------------------------------------------------
// Kernel 6: gather + center + L2-normalize + straight-through identity.
// ---------------------------------------------------------------------------
__global__ __launch_bounds__(256)
void quantize_kernel(const float* __restrict__ inputs,
                     const float* __restrict__ codebook,
                     float* __restrict__ qout)
{
    const int warp = threadIdx.x >> 5;
    const int lane = threadIdx.x & 31;
    const int tok = blockIdx.x * 8 + warp;
    const int idx = g_nn[tok];
    const float* row = codebook + (size_t)idx * D_DIM;

    float4 x[8];
    float sum = 0.f;
#pragma unroll
    for (int c = 0; c < 8; ++c) {
        x[c] = *(const float4*)(row + c * 128 + lane * 4);
        sum += x[c].x + x[c].y + x[c].z + x[c].w;
    }
#pragma unroll
    for (int off = 16; off > 0; off >>= 1)
        sum += __shfl_xor_sync(0xffffffffu, sum, off);
    const float mean = sum * (1.f / (float)D_DIM);

    float ss = 0.f;
#pragma unroll
    for (int c = 0; c < 8; ++c) {
        x[c].x -= mean; x[c].y -= mean; x[c].z -= mean; x[c].w -= mean;
        ss += x[c].x * x[c].x + x[c].y * x[c].y + x[c].z * x[c].z + x[c].w * x[c].w;
    }
#pragma unroll
    for (int off = 16; off > 0; off >>= 1)
        ss += __shfl_xor_sync(0xffffffffu, ss, off);
    const float invn = 1.f / sqrtf(ss);

    const float* xin = inputs + (size_t)tok * D_DIM;
    float* out = qout + (size_t)tok * D_DIM;
#pragma unroll
    for (int c = 0; c < 8; ++c) {
        float4 iv = *(const float4*)(xin + c * 128 + lane * 4);
        float4 v;
        v.x = iv.x + (x[c].x * invn - iv.x);
        v.y = iv.y + (x[c].y * invn - iv.y);
        v.z = iv.z + (x[c].z * invn - iv.z);
        v.w = iv.w + (x[c].w * invn - iv.w);
        *(float4*)(out + c * 128 + lane * 4) = v;
    }
}

// ---------------------------------------------------------------------------
extern "C" void kernel_launch(void* const* d_in, const int* in_sizes, int n_in,
                              void* d_out, int out_size)
{
    const float* inputs   = (const float*)d_in[0];
    const float* codebook = (const float*)d_in[1];
    float* out = (float*)d_out;

    __nv_bfloat16 *logits;
    uint4 *Ahi, *Bhi;
    cudaGetSymbolAddress((void**)&logits, g_logits);
    cudaGetSymbolAddress((void**)&Ahi, g_Ahi);
    cudaGetSymbolAddress((void**)&Bhi, g_Bhi);

    // 0) convert fp32 -> bf16 hi, pre-tiled + swizzled
    split_kernel<<<(M_TOK * 128) / 256, 256>>>(inputs, Ahi, M_TOK * 128, 16, 1);
    split_kernel<<<(K_CODE * 128) / 256, 256>>>(codebook, Bhi, K_CODE * 128, 1, 16);

    // 1) single-split bf16 similarity GEMM, 64x64 warp tiles, 2 CTA/SM
    cudaFuncSetAttribute(gemm_bf16x1_mma_kernel,
                         cudaFuncAttributeMaxDynamicSharedMemorySize, G_SMEM_TOTAL);
    {
        dim3 grid(K_CODE / 128, M_TOK / 128);   // (16, 256), nt fastest
        gemm_bf16x1_mma_kernel<<<grid, 128, G_SMEM_TOTAL>>>(
            (const uint8_t*)Ahi, (const uint8_t*)Bhi, logits);
    }

    // 2) row pass (warp-pair per token, bf16 logits, 2 CTA/SM)
    row_pass_kernel<<<RP_PAIRS / 4, 256>>>(logits);
    // 2b) fp64 refine of near-tied argmax -> final nn_idx
    refine_kernel<<<M_TOK / 8, 256>>>(inputs, codebook, out + NN_OFF);
    // 3) loss reduction
    div_reduce_kernel<<<16, 128>>>();
    finalize2_kernel<<<1, 256>>>();
    // 4) broadcast loss
    fill_loss_kernel<<<8192, 256>>>(out + LOSS_OFF);
    // 5) codebook passthrough
    copy_cb_kernel<<<2048, 256>>>(codebook, out + CB_OFF);
    // 6) quantized rows
    quantize_kernel<<<M_TOK / 8, 256>>>(inputs, codebook, out + QUANT_OFF);
}